// round 2
// baseline (speedup 1.0000x reference)
#include <cuda_runtime.h>
#include <cstdint>

// Problem constants
#define Q      1024
#define D      512
#define NPTS   50000
#define PITCH  50048          // 391 * 128, padded so every GEMM N-tile stores unguarded
#define KNN    10

// Scratch (device globals: allocation-free rule)
__device__ float g_dot[(size_t)Q * PITCH];   // ~205 MB
__device__ float g_x2[Q];
__device__ float g_d2[NPTS];

// ---------------------------------------------------------------------------
// Kernel 0: row squared norms (warp per row) for X and data
// ---------------------------------------------------------------------------
__global__ void norms_kernel(const float* __restrict__ X, const float* __restrict__ data)
{
    int warp = (blockIdx.x * blockDim.x + threadIdx.x) >> 5;
    int lane = threadIdx.x & 31;
    if (warp >= Q + NPTS) return;

    const float* src;
    float* dst;
    int row;
    if (warp < Q) { src = X;    row = warp;      dst = g_x2; }
    else          { src = data; row = warp - Q;  dst = g_d2; }

    const float* p = src + (size_t)row * D;
    float s = 0.f;
    #pragma unroll 4
    for (int k = lane; k < D; k += 32) {
        float v = p[k];
        s = fmaf(v, v, s);
    }
    #pragma unroll
    for (int off = 16; off; off >>= 1)
        s += __shfl_down_sync(0xffffffffu, s, off);
    if (lane == 0) dst[row] = s;
}

// ---------------------------------------------------------------------------
// Kernel 1: SGEMM-NT  dot = X @ data^T   (128x128 tile, BK=8, 8x8 microtile)
// A = X [Q, D] row-major, B = data [NPTS, D] row-major, C = g_dot [Q, PITCH]
// ---------------------------------------------------------------------------
__global__ __launch_bounds__(256, 2) void gemm_nt_kernel(const float* __restrict__ A,
                                                         const float* __restrict__ B)
{
    __shared__ float As[8][128];
    __shared__ float Bs[8][128];

    const int tid = threadIdx.x;
    const int bm  = blockIdx.y * 128;   // query tile base
    const int bn  = blockIdx.x * 128;   // data tile base

    // Global -> smem load mapping: each thread loads one float4 of A and of B.
    const int lr = tid >> 1;            // 0..127 : row within tile
    const int lc = (tid & 1) << 2;      // 0 or 4 : k offset within BK=8

    const float* Ap = A + (size_t)(bm + lr) * D + lc;
    const int    brow = bn + lr;
    const float* Bp = B + (size_t)brow * D + lc;
    const bool   bvalid = (brow < NPTS);

    // Compute mapping: 16x16 thread grid, 8x8 accumulators
    const int tx = tid & 15;
    const int ty = tid >> 4;

    float acc[8][8];
    #pragma unroll
    for (int i = 0; i < 8; ++i)
        #pragma unroll
        for (int j = 0; j < 8; ++j)
            acc[i][j] = 0.f;

    for (int k0 = 0; k0 < D; k0 += 8) {
        float4 a4 = *(const float4*)Ap;
        float4 b4 = bvalid ? *(const float4*)Bp : make_float4(0.f, 0.f, 0.f, 0.f);
        Ap += 8;
        Bp += 8;

        __syncthreads();   // previous tile's compute done before overwrite
        As[lc + 0][lr] = a4.x;
        As[lc + 1][lr] = a4.y;
        As[lc + 2][lr] = a4.z;
        As[lc + 3][lr] = a4.w;
        Bs[lc + 0][lr] = b4.x;
        Bs[lc + 1][lr] = b4.y;
        Bs[lc + 2][lr] = b4.z;
        Bs[lc + 3][lr] = b4.w;
        __syncthreads();

        #pragma unroll
        for (int kk = 0; kk < 8; ++kk) {
            float ar[8], br[8];
            *(float4*)&ar[0] = *(const float4*)&As[kk][ty * 8 + 0];
            *(float4*)&ar[4] = *(const float4*)&As[kk][ty * 8 + 4];
            *(float4*)&br[0] = *(const float4*)&Bs[kk][tx * 8 + 0];
            *(float4*)&br[4] = *(const float4*)&Bs[kk][tx * 8 + 4];
            #pragma unroll
            for (int i = 0; i < 8; ++i)
                #pragma unroll
                for (int j = 0; j < 8; ++j)
                    acc[i][j] = fmaf(ar[i], br[j], acc[i][j]);
        }
    }

    // Store to padded scratch (no guards needed: PITCH covers all N-tiles)
    float* Crow = g_dot + (size_t)(bm + ty * 8) * PITCH + (bn + tx * 8);
    #pragma unroll
    for (int i = 0; i < 8; ++i) {
        float4 v0 = make_float4(acc[i][0], acc[i][1], acc[i][2], acc[i][3]);
        float4 v1 = make_float4(acc[i][4], acc[i][5], acc[i][6], acc[i][7]);
        *(float4*)(Crow + (size_t)i * PITCH + 0) = v0;
        *(float4*)(Crow + (size_t)i * PITCH + 4) = v1;
    }
}

// ---------------------------------------------------------------------------
// Kernel 2: per-query top-10 (ascending sq distance, index tiebreak) + mode
// One block per query, 256 threads.
// Labels buffer may be int32 (JAX default, x64 disabled) or int64. Detect:
// little-endian int64 layout viewed as int32 is [lab,0,lab,0,...] (labels<100),
// so "odd words 1..63 all zero" => int64 (stride 2), else int32 (stride 1).
// ---------------------------------------------------------------------------
__global__ __launch_bounds__(256) void select_kernel(const int* __restrict__ t32,
                                                     float* __restrict__ out)
{
    const int q   = blockIdx.x;
    const int tid = threadIdx.x;
    const float* row = g_dot + (size_t)q * PITCH;
    const float  xq  = g_x2[q];

    const unsigned long long MAXK = ~0ull;
    unsigned long long best[KNN];
    #pragma unroll
    for (int i = 0; i < KNN; ++i) best[i] = MAXK;

    for (int j = tid; j < NPTS; j += 256) {
        float sq = fmaxf(fmaf(-2.f, row[j], xq + g_d2[j]), 0.f);
        unsigned long long key =
            ((unsigned long long)__float_as_uint(sq) << 32) | (unsigned)j;
        if (key < best[KNN - 1]) {
            best[KNN - 1] = key;
            #pragma unroll
            for (int i = KNN - 1; i >= 1; --i) {
                if (best[i] < best[i - 1]) {
                    unsigned long long t = best[i - 1];
                    best[i - 1] = best[i];
                    best[i] = t;
                }
            }
        }
    }

    // Block-wide merge: 10 rounds of min-reduction over each thread's cursor.
    __shared__ unsigned long long red[256];
    __shared__ unsigned long long topk[KNN];
    int ptr = 0;
    for (int r = 0; r < KNN; ++r) {
        unsigned long long my = (ptr < KNN) ? best[ptr] : MAXK;
        red[tid] = my;
        __syncthreads();
        #pragma unroll
        for (int s = 128; s > 0; s >>= 1) {
            if (tid < s) {
                unsigned long long o = red[tid + s];
                if (o < red[tid]) red[tid] = o;
            }
            __syncthreads();
        }
        unsigned long long w = red[0];
        if (my == w && my != MAXK) ++ptr;   // keys unique (idx in low bits)
        if (tid == 0) topk[r] = w;
        __syncthreads();
    }

    // Mode over the 10 neighbor labels: max count, tie -> smallest label
    // (matches argmax over one-hot histogram).
    if (tid == 0) {
        // Detect label element width (see header comment).
        int stride = 2;
        #pragma unroll
        for (int i = 1; i < 64; i += 2)
            if (t32[i] != 0) { stride = 1; break; }

        int lab[KNN];
        #pragma unroll
        for (int r = 0; r < KNN; ++r) {
            unsigned idx = (unsigned)(topk[r] & 0xffffffffu);
            lab[r] = t32[(size_t)idx * stride];
        }

        int bestLab = 0x7fffffff, bestCnt = 0;
        #pragma unroll
        for (int i = 0; i < KNN; ++i) {
            int cnt = 0;
            #pragma unroll
            for (int j = 0; j < KNN; ++j)
                cnt += (lab[j] == lab[i]);
            if (cnt > bestCnt || (cnt == bestCnt && lab[i] < bestLab)) {
                bestCnt = cnt;
                bestLab = lab[i];
            }
        }
        out[q] = (float)bestLab;
    }
}

// ---------------------------------------------------------------------------
extern "C" void kernel_launch(void* const* d_in, const int* in_sizes, int n_in,
                              void* d_out, int out_size)
{
    const float* X       = (const float*)d_in[0];
    const float* data    = (const float*)d_in[1];
    const int*   targets = (const int*)d_in[2];   // int32 or int64 (probed in-kernel)
    float*       out     = (float*)d_out;

    (void)in_sizes; (void)n_in; (void)out_size;

    // norms: one warp per row, 8 warps per block
    int nwarps  = Q + NPTS;
    int nblocks = (nwarps + 7) / 8;
    norms_kernel<<<nblocks, 256>>>(X, data);

    // GEMM: 391 N-tiles x 8 M-tiles
    dim3 grid(PITCH / 128, Q / 128);
    gemm_nt_kernel<<<grid, 256>>>(X, data);

    // top-k + mode: one block per query
    select_kernel<<<Q, 256>>>(targets, out);
}

// round 5
// speedup vs baseline: 3.9296x; 3.9296x over previous
#include <cuda_runtime.h>
#include <cuda_bf16.h>
#include <cstdint>

// Problem constants
#define Q      1024
#define D      512
#define NPTS   50000
#define BM     128
#define BN     128
#define BK     32
#define ITERS  (D / BK)                 // 16
#define NTILES ((NPTS + BN - 1) / BN)   // 391
#define PITCH  (NTILES * BN)            // 50048
#define KNN    10
#define PAD    40                       // padded smem row stride in bf16 (80B)

// Scratch (device globals: allocation-free rule)
__device__ float          g_dot[(size_t)Q * PITCH];  // approx sq distances (~205 MB)
__device__ float          g_x2[Q];
__device__ float          g_d2[NPTS];
__device__ __nv_bfloat16  g_xb[(size_t)Q * D];
__device__ __nv_bfloat16  g_db[(size_t)NPTS * D];

// ---------------------------------------------------------------------------
// helpers
// ---------------------------------------------------------------------------
__device__ __forceinline__ uint32_t smem_u32(const void* p) {
    uint32_t a;
    asm("{ .reg .u64 t; cvta.to.shared.u64 t, %1; cvt.u32.u64 %0, t; }" : "=r"(a) : "l"(p));
    return a;
}
__device__ __forceinline__ void cp_async16(uint32_t saddr, const void* gaddr, uint32_t src_sz) {
    asm volatile("cp.async.cg.shared.global [%0], [%1], 16, %2;"
                 :: "r"(saddr), "l"(gaddr), "r"(src_sz) : "memory");
}
__device__ __forceinline__ void cp_commit() {
    asm volatile("cp.async.commit_group;" ::: "memory");
}
template <int N>
__device__ __forceinline__ void cp_wait() {
    asm volatile("cp.async.wait_group %0;" :: "n"(N) : "memory");
}
__device__ __forceinline__ void ldm_x4(uint32_t& r0, uint32_t& r1, uint32_t& r2, uint32_t& r3,
                                       uint32_t addr) {
    asm volatile("ldmatrix.sync.aligned.m8n8.x4.shared.b16 {%0,%1,%2,%3}, [%4];"
                 : "=r"(r0), "=r"(r1), "=r"(r2), "=r"(r3) : "r"(addr));
}
__device__ __forceinline__ void mma_bf16(float& c0, float& c1, float& c2, float& c3,
                                         uint32_t a0, uint32_t a1, uint32_t a2, uint32_t a3,
                                         uint32_t b0, uint32_t b1) {
    asm volatile(
        "mma.sync.aligned.m16n8k16.row.col.f32.bf16.bf16.f32 "
        "{%0,%1,%2,%3}, {%4,%5,%6,%7}, {%8,%9}, {%0,%1,%2,%3};"
        : "+f"(c0), "+f"(c1), "+f"(c2), "+f"(c3)
        : "r"(a0), "r"(a1), "r"(a2), "r"(a3), "r"(b0), "r"(b1));
}

// ---------------------------------------------------------------------------
// Kernel 0: fused fp32->bf16 convert + row squared norms (warp per row)
// ---------------------------------------------------------------------------
__global__ void convert_norms_kernel(const float* __restrict__ X,
                                     const float* __restrict__ data)
{
    int warp = (blockIdx.x * blockDim.x + threadIdx.x) >> 5;
    int lane = threadIdx.x & 31;
    if (warp >= Q + NPTS) return;

    const float*   src;
    __nv_bfloat16* dstb;
    float*         dstn;
    int row;
    if (warp < Q) { src = X;    row = warp;     dstb = g_xb; dstn = g_x2; }
    else          { src = data; row = warp - Q; dstb = g_db; dstn = g_d2; }

    const float4* s4 = (const float4*)(src + (size_t)row * D);
    uint2*        d8 = (uint2*)(dstb + (size_t)row * D);

    float s = 0.f;
    #pragma unroll
    for (int it = 0; it < 4; ++it) {
        int i = it * 32 + lane;
        float4 v = s4[i];
        s = fmaf(v.x, v.x, s);
        s = fmaf(v.y, v.y, s);
        s = fmaf(v.z, v.z, s);
        s = fmaf(v.w, v.w, s);
        __nv_bfloat162 h0 = __floats2bfloat162_rn(v.x, v.y);
        __nv_bfloat162 h1 = __floats2bfloat162_rn(v.z, v.w);
        uint2 w;
        w.x = *reinterpret_cast<uint32_t*>(&h0);
        w.y = *reinterpret_cast<uint32_t*>(&h1);
        d8[i] = w;
    }
    #pragma unroll
    for (int off = 16; off; off >>= 1)
        s += __shfl_down_sync(0xffffffffu, s, off);
    if (lane == 0) dstn[row] = s;
}

// ---------------------------------------------------------------------------
// Kernel 1: bf16 mma.sync GEMM tile (128x128, K=512), epilogue writes approx
// squared distance  s = max(x2 + d2 - 2*dot, 0)  to g_dot.
// 8 warps in 2(m) x 4(n); each warp computes 64x32 via m16n8k16.
// ---------------------------------------------------------------------------
__global__ void __launch_bounds__(256, 2) gemm_mma_kernel()
{
    __shared__ __align__(16) __nv_bfloat16 As[2][BM * PAD];
    __shared__ __align__(16) __nv_bfloat16 Bs[2][BN * PAD];

    const int tid    = threadIdx.x;
    const int wid    = tid >> 5;
    const int lane   = tid & 31;
    const int warp_m = wid >> 2;    // 0..1
    const int warp_n = wid & 3;     // 0..3
    const int bn     = blockIdx.x * BN;
    const int bm     = blockIdx.y * BM;

    // cp.async per-thread mapping: 512 16B-chunks per tile, 2 per thread
    const int r0 = tid >> 2,           c0 = tid & 3;           // chunk tid
    const int r1 = (tid + 256) >> 2,   c1 = (tid + 256) & 3;   // chunk tid+256

    const uint32_t sA = smem_u32(As);
    const uint32_t sB = smem_u32(Bs);
    const uint32_t aS0 = sA + (r0 * PAD + c0 * 8) * 2;
    const uint32_t aS1 = sA + (r1 * PAD + c1 * 8) * 2;
    const uint32_t bS0 = sB + (r0 * PAD + c0 * 8) * 2;
    const uint32_t bS1 = sB + (r1 * PAD + c1 * 8) * 2;
    const size_t   aG0 = (size_t)(bm + r0) * D + c0 * 8;
    const size_t   aG1 = (size_t)(bm + r1) * D + c1 * 8;
    const size_t   bG0 = (size_t)(bn + r0) * D + c0 * 8;
    const size_t   bG1 = (size_t)(bn + r1) * D + c1 * 8;
    const uint32_t bV0 = (bn + r0 < NPTS) ? 16u : 0u;
    const uint32_t bV1 = (bn + r1 < NPTS) ? 16u : 0u;
    const uint32_t BUFA = BM * PAD * 2;   // bytes per A buffer
    const uint32_t BUFB = BN * PAD * 2;

    // ldmatrix per-lane bases (element offsets; see fragment-mapping comment)
    // A: rows (lane&15), col8 group (lane>>4)
    const uint32_t aLd = sA + (((warp_m * 64) + (lane & 15)) * PAD + (lane >> 4) * 8) * 2;
    // B: rows n (lane&7), k octet (lane>>3)
    const uint32_t bLd = sB + (((warp_n * 32) + (lane & 7)) * PAD + (lane >> 3) * 8) * 2;

    float acc[4][4][4];
    #pragma unroll
    for (int i = 0; i < 4; ++i)
        #pragma unroll
        for (int j = 0; j < 4; ++j)
            #pragma unroll
            for (int e = 0; e < 4; ++e)
                acc[i][j][e] = 0.f;

    // prologue: load iter 0 into buf 0
    cp_async16(aS0, g_xb + aG0, 16);
    cp_async16(aS1, g_xb + aG1, 16);
    cp_async16(bS0, g_db + bG0, bV0);
    cp_async16(bS1, g_db + bG1, bV1);
    cp_commit();

    for (int it = 0; it < ITERS; ++it) {
        const int      buf  = it & 1;
        const uint32_t offA = buf ? BUFA : 0;
        const uint32_t offB = buf ? BUFB : 0;

        if (it + 1 < ITERS) {
            const int      nb   = (it + 1) & 1;
            const uint32_t nA   = nb ? BUFA : 0;
            const uint32_t nB   = nb ? BUFB : 0;
            const int      k0   = (it + 1) * BK;
            cp_async16(aS0 + nA, g_xb + aG0 + k0, 16);
            cp_async16(aS1 + nA, g_xb + aG1 + k0, 16);
            cp_async16(bS0 + nB, g_db + bG0 + k0, bV0);
            cp_async16(bS1 + nB, g_db + bG1 + k0, bV1);
            cp_commit();
            cp_wait<1>();
        } else {
            cp_wait<0>();
        }
        __syncthreads();

        // B fragments: one x4 per n-tile covers k 0..31 (b[nt][0..1]=ks0, [2..3]=ks1)
        uint32_t b[4][4];
        #pragma unroll
        for (int nt = 0; nt < 4; ++nt)
            ldm_x4(b[nt][0], b[nt][1], b[nt][2], b[nt][3],
                   bLd + offB + (nt * 8 * PAD) * 2);

        #pragma unroll
        for (int ks = 0; ks < 2; ++ks) {
            uint32_t a[4][4];
            #pragma unroll
            for (int mt = 0; mt < 4; ++mt)
                ldm_x4(a[mt][0], a[mt][1], a[mt][2], a[mt][3],
                       aLd + offA + (mt * 16 * PAD + ks * 16) * 2);
            #pragma unroll
            for (int mt = 0; mt < 4; ++mt)
                #pragma unroll
                for (int nt = 0; nt < 4; ++nt)
                    mma_bf16(acc[mt][nt][0], acc[mt][nt][1], acc[mt][nt][2], acc[mt][nt][3],
                             a[mt][0], a[mt][1], a[mt][2], a[mt][3],
                             b[nt][ks * 2], b[nt][ks * 2 + 1]);
        }
        __syncthreads();
    }

    // stage x2 (local m) and d2 (local n, +inf pad) in smem (buffers dead now)
    float* s_x2 = (float*)As;
    float* s_d2 = s_x2 + BM;
    if (tid < BM) s_x2[tid] = g_x2[bm + tid];
    else if (tid < BM + BN) {
        int gn = bn + tid - BM;
        s_d2[tid - BM] = (gn < NPTS) ? g_d2[gn] : __int_as_float(0x7f800000);
    }
    __syncthreads();

    // epilogue: c0,c1 -> row rA, cols cl,cl+1 ; c2,c3 -> row rA+8
    #pragma unroll
    for (int mt = 0; mt < 4; ++mt) {
        const int rA = warp_m * 64 + mt * 16 + (lane >> 2);
        const float x2a = s_x2[rA];
        const float x2b = s_x2[rA + 8];
        float* rowA = g_dot + (size_t)(bm + rA) * PITCH + bn;
        float* rowB = rowA + (size_t)8 * PITCH;
        #pragma unroll
        for (int nt = 0; nt < 4; ++nt) {
            const int cl = warp_n * 32 + nt * 8 + (lane & 3) * 2;
            const float d2a = s_d2[cl], d2b = s_d2[cl + 1];
            float2 v0, v1;
            v0.x = fmaxf(fmaf(-2.f, acc[mt][nt][0], x2a + d2a), 0.f);
            v0.y = fmaxf(fmaf(-2.f, acc[mt][nt][1], x2a + d2b), 0.f);
            v1.x = fmaxf(fmaf(-2.f, acc[mt][nt][2], x2b + d2a), 0.f);
            v1.y = fmaxf(fmaf(-2.f, acc[mt][nt][3], x2b + d2b), 0.f);
            *(float2*)(rowA + cl) = v0;
            *(float2*)(rowB + cl) = v1;
        }
    }
}

// ---------------------------------------------------------------------------
// Kernel 2: per-query approx top-16 -> exact fp32 re-rank -> top-10 -> mode
// One block per query, 256 threads.
// ---------------------------------------------------------------------------
#define KLOC 6    // per-thread approx candidates
#define KSEL 16   // global approx candidates re-ranked exactly

__global__ void __launch_bounds__(256) select_kernel(const float* __restrict__ X,
                                                     const float* __restrict__ data,
                                                     const int* __restrict__ t32,
                                                     float* __restrict__ out)
{
    const int q   = blockIdx.x;
    const int tid = threadIdx.x;

    __shared__ float sx[D];
    sx[tid]       = X[(size_t)q * D + tid];
    sx[tid + 256] = X[(size_t)q * D + 256 + tid];

    // Phase 1: per-thread top-6 over approx scores
    const float* row = g_dot + (size_t)q * PITCH;
    const unsigned long long MAXK = ~0ull;
    unsigned long long best[KLOC];
    #pragma unroll
    for (int i = 0; i < KLOC; ++i) best[i] = MAXK;

    for (int j = tid; j < NPTS; j += 256) {
        float s = row[j];
        unsigned long long key =
            ((unsigned long long)__float_as_uint(s) << 32) | (unsigned)j;
        if (key < best[KLOC - 1]) {
            best[KLOC - 1] = key;
            #pragma unroll
            for (int i = KLOC - 1; i >= 1; --i) {
                if (best[i] < best[i - 1]) {
                    unsigned long long t = best[i - 1];
                    best[i - 1] = best[i];
                    best[i] = t;
                }
            }
        }
    }

    // Phase 2: 16 rounds of block-wide min-merge
    __shared__ unsigned long long red[256];
    __shared__ unsigned long long top16[KSEL];
    int ptr = 0;
    for (int r = 0; r < KSEL; ++r) {
        unsigned long long my = (ptr < KLOC) ? best[ptr] : MAXK;
        red[tid] = my;
        __syncthreads();
        #pragma unroll
        for (int s = 128; s > 0; s >>= 1) {
            if (tid < s) {
                unsigned long long o = red[tid + s];
                if (o < red[tid]) red[tid] = o;
            }
            __syncthreads();
        }
        unsigned long long w = red[0];
        if (my == w && my != MAXK) ++ptr;   // keys unique (idx in low bits)
        if (tid == 0) top16[r] = w;
        __syncthreads();
    }

    // Phase 3: exact fp32 re-rank of the 16 candidates (one warp each, strided)
    __shared__ unsigned long long ex[KSEL];
    const int wid  = tid >> 5;
    const int lane = tid & 31;
    const float x2q = g_x2[q];
    for (int t = wid; t < KSEL; t += 8) {
        unsigned c = (unsigned)(top16[t] & 0xffffffffu);
        const float* dr = data + (size_t)c * D;
        float dot = 0.f;
        #pragma unroll 4
        for (int k = lane; k < D; k += 32)
            dot = fmaf(sx[k], dr[k], dot);
        #pragma unroll
        for (int off = 16; off; off >>= 1)
            dot += __shfl_down_sync(0xffffffffu, dot, off);
        if (lane == 0) {
            float sq = fmaxf(fmaf(-2.f, dot, x2q + g_d2[c]), 0.f);
            ex[t] = ((unsigned long long)__float_as_uint(sq) << 32) | c;
        }
    }
    __syncthreads();

    // Phase 4: sort 16, labels of first 10, mode (smallest label on tie)
    if (tid == 0) {
        unsigned long long a[KSEL];
        #pragma unroll
        for (int i = 0; i < KSEL; ++i) a[i] = ex[i];
        #pragma unroll
        for (int i = 1; i < KSEL; ++i) {
            unsigned long long v = a[i];
            int j = i - 1;
            while (j >= 0 && a[j] > v) { a[j + 1] = a[j]; --j; }
            a[j + 1] = v;
        }

        // targets element width probe (int32 vs int64 little-endian)
        int stride = 2;
        #pragma unroll
        for (int i = 1; i < 64; i += 2)
            if (t32[i] != 0) { stride = 1; break; }

        int lab[KNN];
        #pragma unroll
        for (int r = 0; r < KNN; ++r)
            lab[r] = t32[(size_t)(unsigned)(a[r] & 0xffffffffu) * stride];

        int bestLab = 0x7fffffff, bestCnt = 0;
        #pragma unroll
        for (int i = 0; i < KNN; ++i) {
            int cnt = 0;
            #pragma unroll
            for (int j = 0; j < KNN; ++j)
                cnt += (lab[j] == lab[i]);
            if (cnt > bestCnt || (cnt == bestCnt && lab[i] < bestLab)) {
                bestCnt = cnt;
                bestLab = lab[i];
            }
        }
        out[q] = (float)bestLab;
    }
}

// ---------------------------------------------------------------------------
extern "C" void kernel_launch(void* const* d_in, const int* in_sizes, int n_in,
                              void* d_out, int out_size)
{
    const float* X       = (const float*)d_in[0];
    const float* data    = (const float*)d_in[1];
    const int*   targets = (const int*)d_in[2];
    float*       out     = (float*)d_out;

    (void)in_sizes; (void)n_in; (void)out_size;

    // convert + norms: warp per row
    int nwarps  = Q + NPTS;
    int nblocks = (nwarps + 7) / 8;
    convert_norms_kernel<<<nblocks, 256>>>(X, data);

    // mma.sync GEMM: 391 N-tiles x 8 M-tiles
    dim3 grid(NTILES, Q / BM);
    gemm_mma_kernel<<<grid, 256>>>();

    // approx select + exact re-rank + mode
    select_kernel<<<Q, 256>>>(X, data, targets, out);
}